// round 13
// baseline (speedup 1.0000x reference)
#include <cuda_runtime.h>
#include <cstdint>

#define BB 8
#define CC 8
#define HH 512
#define WW 512
#define PLANE (HH*WW)                 // 262144
#define PIX   (BB*HH*WW)              // 2097152
#define NEL   (BB*CC*HH*WW)           // 16777216

#define TPB   256                     // 8 warps; 2 px per thread = full 512-col row
#define RPT   8                       // rows per thread
#define NBY   (HH/RPT)                // 64
#define NBLK  (NBY*BB)                // 512

__device__ double       g_acc;        // zero-init; reset by last block each run
__device__ unsigned int g_count;      // wraps to 0 via atomicInc

// sigmoid via single-MUFU tanh.approx: sigma(x) = 0.5 + 0.5*tanh(x/2)
__device__ __forceinline__ float sigt(float x) {
    float t;
    asm("tanh.approx.f32 %0, %1;" : "=f"(t) : "f"(0.5f * x));
    return fmaf(0.5f, t, 0.5f);
}
__device__ __forceinline__ float2 ld2(const float* __restrict__ p) {
    return *reinterpret_cast<const float2*>(p);
}
__device__ __forceinline__ float clog(float x) {
    return fmaxf(__logf(x), -100.0f);   // matches jnp.clip(log(x), -100)
}

// value at col w0-1 of same row/channel: left lane's a[1]; lane-0 fixup LDG
__device__ __forceinline__ float getL(const float a[2], const float* __restrict__ g,
                                      bool ok, int lane) {
    float v = __shfl_up_sync(0xffffffffu, a[1], 1);
    if (lane == 0) v = ok ? sigt(__ldg(g)) : 0.0f;
    return v;
}
// value at col w0+2: right lane's a[0]; lane-31 fixup LDG
__device__ __forceinline__ float getR(const float a[2], const float* __restrict__ g,
                                      bool ok, int lane) {
    float v = __shfl_down_sync(0xffffffffu, a[0], 1);
    if (lane == 31) v = ok ? sigt(__ldg(g)) : 0.0f;
    return v;
}

// con_target bitmasks (2 px x 8 bits) + 2 target bits packed into one u32
__device__ __forceinline__ unsigned build_mask(
        const float* __restrict__ cb, const float* __restrict__ tb) {
    unsigned m = 0;
#pragma unroll
    for (int c = 0; c < 8; c++) {
        float2 t = ld2(cb + c * PLANE);
        m |= ((unsigned)(t.x > 0.5f)) << c;
        m |= ((unsigned)(t.y > 0.5f)) << (8 + c);
    }
    float2 tg = ld2(tb);
    m |= ((unsigned)(tg.x > 0.5f)) << 16;
    m |= ((unsigned)(tg.y > 0.5f)) << 17;
    return m;
}

// votes + loss terms for one row of a 2-pixel strip.
// Shm: ch5,6,7 sigmoids at row r-1; C: all 8 ch at row r; Sn: ch0,1,2 at row r+1.
__device__ __forceinline__ float row_votes(
    const float Shm[3][2], const float C[8][2], const float Sn[3][2],
    const float* __restrict__ px,
    bool wlo, bool whi, int lane, bool hmok, bool hpok,
    unsigned mp, int pass)
{
    float L7 = getL(Shm[2], px - WW + 7 * PLANE - 1, hmok && !wlo, lane);
    float R5 = getR(Shm[0], px - WW + 5 * PLANE + 2, hmok && !whi, lane);
    float L4 = getL(C[4],   px      + 4 * PLANE - 1, !wlo,         lane);
    float R3 = getR(C[3],   px      + 3 * PLANE + 2, !whi,         lane);
    float L2 = getL(Sn[2],  px + WW + 2 * PLANE - 1, hpok && !wlo, lane);
    float R0 = getR(Sn[0],  px + WW + 0 * PLANE + 2, hpok && !whi, lane);

    float accb = 0.0f, accp = 0.0f;
#pragma unroll
    for (int p = 0; p < 2; p++) {
        float nb[8];
        nb[0] = (p == 0) ? L7 : Shm[2][0];   // c7(r-1, w-1)
        nb[1] = Shm[1][p];                   // c6(r-1, w)
        nb[2] = (p == 1) ? R5 : Shm[0][1];   // c5(r-1, w+1)
        nb[3] = (p == 0) ? L4 : C[4][0];     // c4(r,   w-1)
        nb[4] = (p == 1) ? R3 : C[3][1];     // c3(r,   w+1)
        nb[5] = (p == 0) ? L2 : Sn[2][0];    // c2(r+1, w-1)
        nb[6] = Sn[1][p];                    // c1(r+1, w)
        nb[7] = (p == 1) ? R0 : Sn[0][1];    // c0(r+1, w+1)

        unsigned m = (mp >> (8 * p)) & 0xFFu;
        bool T = (mp >> (16 + p)) & 1u;

        // fast path: raw products, one log per side; exact fallback when the
        // product underflows/zeros (padded borders) — matches per-term clamp.
        float pA = 1.f, pB = 1.f, glo = 0.f, mn = 1e30f;
#pragma unroll
        for (int k = 0; k < 8; k++) {
            float s = C[k][p];
            float v = s * nb[k];
            glo += v;
            if (pass == 1) mn = fminf(mn, v);
            bool t = (m >> k) & 1u;
            pA *= t ? v : 1.0f - v;
            pB *= t ? s : 1.0f - s;
        }

        float bic, co;
        if (pA >= 1e-37f) {
            bic = __logf(pA);
        } else {                       // rare: border zeros / extreme tails
            bic = 0.0f;
#pragma unroll
            for (int k = 0; k < 8; k++) {
                float v = C[k][p] * nb[k];
                bool t = (m >> k) & 1u;
                bic += clog(t ? v : 1.0f - v);
            }
        }
        if (pB >= 1e-37f) {
            co = __logf(pB);
        } else {
            co = 0.0f;
#pragma unroll
            for (int k = 0; k < 8; k++) {
                float s = C[k][p];
                bool t = (m >> k) & 1u;
                co += clog(t ? s : 1.0f - s);
            }
        }
        accb += 0.2f * bic + 0.8f * co;

        float g = glo * 0.125f;
        float x;
        if (pass == 0) {
            x = T ? g : 1.0f - g;                        // bce_loss1
        } else {
            bool edge = (m != 0u) && (m != 255u);
            float de  = edge ? (1.0f - mn) : g;          // decouple map
            x = T ? de : 1.0f - de;
        }
        accp += clog(x);
    }
    return accb * (1.0f / (float)NEL) + accp * (1.0f / (float)PIX);
}

__global__ void __launch_bounds__(TPB, 3)
bicon_loss_kernel(const float* __restrict__ atts,
                  const float* __restrict__ dets,
                  const float* __restrict__ target,
                  const float* __restrict__ con,
                  float* __restrict__ out)
{
    __shared__ unsigned mk[RPT * TPB];   // 8 KB per-thread mask cache
    __shared__ float wsum[TPB / 32];

    const int tid  = threadIdx.x;
    const int lane = tid & 31;
    const int bid  = blockIdx.x;
    const int band  = bid & (NBY - 1);
    const int b     = bid / NBY;
    const int w0 = tid * 2;                 // 2-px strip; block covers full row
    const int r0 = band * RPT;
    const bool wlo = (w0 == 0), whi = (w0 + 2 == WW);

    const size_t bst  = (size_t)CC * PLANE;
    const size_t soff = (size_t)r0 * WW + w0;   // strip offset within batch image

    float contrib = 0.0f;

#pragma unroll 1
    for (int pass = 0; pass < 2; pass++) {
        const float* px = (pass ? dets : atts) + (size_t)b * bst + soff;

        // prologue: row r0-1 channels 5..7; row r0 all 8
        float Shm[3][2];
        if (r0 > 0) {
#pragma unroll
            for (int j = 0; j < 3; j++) {
                float2 x = ld2(px - WW + (5 + j) * PLANE);
                Shm[j][0] = sigt(x.x); Shm[j][1] = sigt(x.y);
            }
        } else {
#pragma unroll
            for (int j = 0; j < 3; j++) { Shm[j][0] = 0.0f; Shm[j][1] = 0.0f; }
        }
        float C[8][2];
#pragma unroll
        for (int c = 0; c < 8; c++) {
            float2 x = ld2(px + c * PLANE);
            C[c][0] = sigt(x.x); C[c][1] = sigt(x.y);
        }

        const float* cpx = con + (size_t)b * bst + soff;       // rolling con ptr
        const float* tpx = target + (size_t)b * PLANE + soff;  // rolling target ptr

#pragma unroll 1
        for (int i = 0; i < RPT - 1; i++) {
            const int r = r0 + i;
            unsigned mp;
            if (pass == 0) {
                mp = build_mask(cpx, tpx);
                mk[i * TPB + tid] = mp;          // private slot, no barrier needed
            } else {
                mp = mk[i * TPB + tid];
            }
            // full next-row prefetch (8 independent LDG.64 in flight)
            float N[8][2];
#pragma unroll
            for (int c = 0; c < 8; c++) {
                float2 x = ld2(px + WW + c * PLANE);
                N[c][0] = sigt(x.x); N[c][1] = sigt(x.y);
            }

            contrib += row_votes(Shm, C, N, px, wlo, whi, lane,
                                 r > 0, true, mp, pass);
            // roll
#pragma unroll
            for (int j = 0; j < 3; j++) {
                Shm[j][0] = C[5 + j][0]; Shm[j][1] = C[5 + j][1];
            }
#pragma unroll
            for (int c = 0; c < 8; c++) { C[c][0] = N[c][0]; C[c][1] = N[c][1]; }
            px  += WW;
            cpx += WW;
            tpx += WW;
        }
        {   // last row of band: next row needs only channels 0..2
            const int r = r0 + RPT - 1;
            unsigned mp;
            if (pass == 0) {
                mp = build_mask(cpx, tpx);
                mk[(RPT - 1) * TPB + tid] = mp;
            } else {
                mp = mk[(RPT - 1) * TPB + tid];
            }
            const bool hpok = (r + 1 < HH);
            float Sn[3][2];
            if (hpok) {
#pragma unroll
                for (int c = 0; c < 3; c++) {
                    float2 x = ld2(px + WW + c * PLANE);
                    Sn[c][0] = sigt(x.x); Sn[c][1] = sigt(x.y);
                }
            } else {
#pragma unroll
                for (int c = 0; c < 3; c++) { Sn[c][0] = 0.0f; Sn[c][1] = 0.0f; }
            }
            contrib += row_votes(Shm, C, Sn, px, wlo, whi, lane,
                                 true, hpok, mp, pass);
        }
    }

    // block reduction: warp shfl -> smem -> one double atomic per block
#pragma unroll
    for (int o = 16; o > 0; o >>= 1)
        contrib += __shfl_down_sync(0xFFFFFFFFu, contrib, o);
    if (lane == 0) wsum[tid >> 5] = contrib;
    __syncthreads();

    if (tid == 0) {
        float s = 0.0f;
#pragma unroll
        for (int i = 0; i < TPB / 32; i++) s += wsum[i];
        atomicAdd(&g_acc, (double)s);
        __threadfence();
        unsigned old = atomicInc(&g_count, NBLK - 1u);   // wraps to 0 on last
        if (old == NBLK - 1u) {
            unsigned long long raw =
                atomicExch((unsigned long long*)&g_acc, 0ULL);
            out[0] = -(float)__longlong_as_double(raw);
        }
    }
}

extern "C" void kernel_launch(void* const* d_in, const int* in_sizes, int n_in,
                              void* d_out, int out_size) {
    const float* atts   = (const float*)d_in[0];
    const float* dets   = (const float*)d_in[1];
    const float* target = (const float*)d_in[2];
    const float* con    = (const float*)d_in[3];
    float* out = (float*)d_out;

    bicon_loss_kernel<<<NBLK, TPB>>>(atts, dets, target, con, out);
}